// round 1
// baseline (speedup 1.0000x reference)
#include <cuda_runtime.h>

#define NFFT 512
#define ROWS_PER_BLK 4
#define THREADS (ROWS_PER_BLK * 64)
#define PADDED 576   /* 512 + 512/8 : pad one float2 per 8 to break bank conflicts */

struct cplx { float re, im; };

__device__ __forceinline__ cplx cadd(cplx a, cplx b) { return {a.re + b.re, a.im + b.im}; }
__device__ __forceinline__ cplx csub(cplx a, cplx b) { return {a.re - b.re, a.im - b.im}; }
__device__ __forceinline__ cplx cmul(cplx a, cplx b) {
    return {fmaf(a.re, b.re, -a.im * b.im), fmaf(a.re, b.im, a.im * b.re)};
}
// multiply by -i : (x + iy)*(-i) = y - ix
__device__ __forceinline__ cplx mul_mi(cplx a) { return {a.im, -a.re}; }

// Forward DFT-8: b[k] = sum_r a[r] * exp(-2*pi*i*r*k/8)
__device__ __forceinline__ void dft8(const cplx* a, cplx* b) {
    const float S = 0.70710678118654752440f;
    // even half: DFT4 of a0,a2,a4,a6
    cplx e0 = cadd(a[0], a[4]), e1 = csub(a[0], a[4]);
    cplx e2 = cadd(a[2], a[6]), e3 = csub(a[2], a[6]);
    cplx E0 = cadd(e0, e2), E2 = csub(e0, e2);
    cplx m3 = mul_mi(e3);
    cplx E1 = cadd(e1, m3), E3 = csub(e1, m3);
    // odd half: DFT4 of a1,a3,a5,a7
    cplx o0 = cadd(a[1], a[5]), o1 = csub(a[1], a[5]);
    cplx o2 = cadd(a[3], a[7]), o3 = csub(a[3], a[7]);
    cplx O0 = cadd(o0, o2), O2 = csub(o0, o2);
    cplx n3 = mul_mi(o3);
    cplx O1 = cadd(o1, n3), O3 = csub(o1, n3);
    // w8^1 = S(1-i), w8^2 = -i, w8^3 = -S(1+i)
    cplx O1w = { S * (O1.re + O1.im), S * (O1.im - O1.re) };
    cplx O2w = mul_mi(O2);
    cplx O3w = { S * (O3.im - O3.re), -S * (O3.re + O3.im) };
    b[0] = cadd(E0, O0);  b[4] = csub(E0, O0);
    b[1] = cadd(E1, O1w); b[5] = csub(E1, O1w);
    b[2] = cadd(E2, O2w); b[6] = csub(E2, O2w);
    b[3] = cadd(E3, O3w); b[7] = csub(E3, O3w);
}

__device__ __forceinline__ int pad(int idx) { return idx + (idx >> 3); }

__global__ __launch_bounds__(THREADS)
void range_fft512_kernel(const float* __restrict__ xre,
                         const float* __restrict__ xim,
                         const float* __restrict__ wre,
                         const float* __restrict__ wim,
                         float2* __restrict__ out,
                         int nrows)
{
    __shared__ float2 tw[NFFT];                       // exp(-2*pi*i*j/512), j=0..511 (row 1 of W)
    __shared__ float2 buf[ROWS_PER_BLK][2][PADDED];   // ping-pong per row

    const int tid = threadIdx.x;

    // twiddle table from the provided DFT matrix row h=1 (exact reference weights)
    for (int j = tid; j < NFFT; j += THREADS)
        tw[j] = make_float2(wre[NFFT + j], wim[NFFT + j]);

    const int r_in_blk = tid >> 6;
    const int lane     = tid & 63;
    long long row = (long long)blockIdx.x * ROWS_PER_BLK + r_in_blk;
    const bool valid = row < nrows;
    long long srow = valid ? row : 0;   // clamp loads; all threads must reach barriers

    const float* xr = xre + srow * NFFT;
    const float* xi = xim + srow * NFFT;

    __syncthreads();

    // ---- stage 0: n=512, s=1, m=64. p = lane, q = 0. gmem -> bufA ----
    {
        cplx a[8], b[8];
        #pragma unroll
        for (int r = 0; r < 8; r++) {
            a[r].re = xr[lane + 64 * r];
            a[r].im = xi[lane + 64 * r];
        }
        dft8(a, b);
        const int p = lane;
        #pragma unroll
        for (int k = 0; k < 8; k++) {
            cplx c;
            if (k == 0) c = b[0];
            else {
                float2 t = tw[p * k];          // exp(-2*pi*i*p*k/512)
                c = cmul(b[k], cplx{t.x, t.y});
            }
            buf[r_in_blk][0][pad(8 * p + k)] = make_float2(c.re, c.im);
        }
    }
    __syncthreads();

    // ---- stage 1: n=64, s=8, m=8. p = lane>>3, q = lane&7. bufA -> bufB ----
    {
        const int p = lane >> 3, q = lane & 7;
        cplx a[8], b[8];
        #pragma unroll
        for (int r = 0; r < 8; r++) {
            float2 v = buf[r_in_blk][0][pad(q + 8 * p + 64 * r)];
            a[r] = {v.x, v.y};
        }
        dft8(a, b);
        #pragma unroll
        for (int k = 0; k < 8; k++) {
            cplx c;
            if (k == 0) c = b[0];
            else {
                float2 t = tw[8 * p * k];      // exp(-2*pi*i*p*k/64)
                c = cmul(b[k], cplx{t.x, t.y});
            }
            buf[r_in_blk][1][pad(q + 64 * p + 8 * k)] = make_float2(c.re, c.im);
        }
    }
    __syncthreads();

    // ---- stage 2: n=8, s=64, m=1. p=0 (twiddle==1), q = lane. bufB -> gmem ----
    {
        cplx a[8], b[8];
        #pragma unroll
        for (int r = 0; r < 8; r++) {
            float2 v = buf[r_in_blk][1][pad(lane + 64 * r)];
            a[r] = {v.x, v.y};
        }
        dft8(a, b);
        if (valid) {
            float2* o = out + row * NFFT;      // interleaved (re, im) = stack(..., -1)
            #pragma unroll
            for (int k = 0; k < 8; k++)
                o[lane + 64 * k] = make_float2(b[k].re, b[k].im);
        }
    }
}

extern "C" void kernel_launch(void* const* d_in, const int* in_sizes, int n_in,
                              void* d_out, int out_size) {
    const float* xre = (const float*)d_in[0];
    const float* xim = (const float*)d_in[1];
    const float* wre = (const float*)d_in[2];
    const float* wim = (const float*)d_in[3];
    (void)n_in; (void)out_size;

    int nrows = in_sizes[0] / NFFT;   // 8*16*256 = 32768
    int grid  = (nrows + ROWS_PER_BLK - 1) / ROWS_PER_BLK;
    range_fft512_kernel<<<grid, THREADS>>>(xre, xim, wre, wim, (float2*)d_out, nrows);
}

// round 2
// speedup vs baseline: 1.0617x; 1.0617x over previous
#include <cuda_runtime.h>

#define NFFT 512
#define ROWS_PER_BLK 2
#define THREADS (ROWS_PER_BLK * 64)
#define PADDED 576   /* 512 + 512/8 : pad one float2 per 8 to soften bank conflicts */

struct cplx { float re, im; };

__device__ __forceinline__ cplx cadd(cplx a, cplx b) { return {a.re + b.re, a.im + b.im}; }
__device__ __forceinline__ cplx csub(cplx a, cplx b) { return {a.re - b.re, a.im - b.im}; }
__device__ __forceinline__ cplx cmul(cplx a, cplx b) {
    return {fmaf(a.re, b.re, -a.im * b.im), fmaf(a.re, b.im, a.im * b.re)};
}
// multiply by -i : (x + iy)*(-i) = y - ix
__device__ __forceinline__ cplx mul_mi(cplx a) { return {a.im, -a.re}; }

// Forward DFT-8: b[k] = sum_r a[r] * exp(-2*pi*i*r*k/8)
__device__ __forceinline__ void dft8(const cplx* a, cplx* b) {
    const float S = 0.70710678118654752440f;
    cplx e0 = cadd(a[0], a[4]), e1 = csub(a[0], a[4]);
    cplx e2 = cadd(a[2], a[6]), e3 = csub(a[2], a[6]);
    cplx E0 = cadd(e0, e2), E2 = csub(e0, e2);
    cplx m3 = mul_mi(e3);
    cplx E1 = cadd(e1, m3), E3 = csub(e1, m3);
    cplx o0 = cadd(a[1], a[5]), o1 = csub(a[1], a[5]);
    cplx o2 = cadd(a[3], a[7]), o3 = csub(a[3], a[7]);
    cplx O0 = cadd(o0, o2), O2 = csub(o0, o2);
    cplx n3 = mul_mi(o3);
    cplx O1 = cadd(o1, n3), O3 = csub(o1, n3);
    cplx O1w = { S * (O1.re + O1.im), S * (O1.im - O1.re) };
    cplx O2w = mul_mi(O2);
    cplx O3w = { S * (O3.im - O3.re), -S * (O3.re + O3.im) };
    b[0] = cadd(E0, O0);  b[4] = csub(E0, O0);
    b[1] = cadd(E1, O1w); b[5] = csub(E1, O1w);
    b[2] = cadd(E2, O2w); b[6] = csub(E2, O2w);
    b[3] = cadd(E3, O3w); b[7] = csub(E3, O3w);
}

__device__ __forceinline__ int pad(int idx) { return idx + (idx >> 3); }

__global__ __launch_bounds__(THREADS, 12)
void range_fft512_kernel(const float* __restrict__ xre,
                         const float* __restrict__ xim,
                         const float* __restrict__ wre,
                         const float* __restrict__ wim,
                         float2* __restrict__ out,
                         int nrows)
{
    __shared__ float2 tw[NFFT];                     // exp(-2*pi*i*j/512) = row 1 of W
    __shared__ float2 buf[ROWS_PER_BLK][PADDED];    // single buffer, reused across stages

    const int tid = threadIdx.x;

    for (int j = tid; j < NFFT; j += THREADS)
        tw[j] = make_float2(wre[NFFT + j], wim[NFFT + j]);

    const int r_in_blk = tid >> 6;
    const int lane     = tid & 63;
    long long row = (long long)blockIdx.x * ROWS_PER_BLK + r_in_blk;
    const bool valid = row < nrows;
    long long srow = valid ? row : 0;   // clamp loads; all threads must reach barriers

    const float* xr = xre + srow * NFFT;
    const float* xi = xim + srow * NFFT;

    __syncthreads();

    // ---- stage 0: n=512, s=1. p = lane. gmem -> buf ----
    {
        cplx a[8], b[8];
        #pragma unroll
        for (int r = 0; r < 8; r++) {
            a[r].re = __ldcs(xr + lane + 64 * r);
            a[r].im = __ldcs(xi + lane + 64 * r);
        }
        dft8(a, b);
        const int p = lane;
        #pragma unroll
        for (int k = 0; k < 8; k++) {
            cplx c;
            if (k == 0) c = b[0];
            else {
                float2 t = tw[p * k];          // exp(-2*pi*i*p*k/512)
                c = cmul(b[k], cplx{t.x, t.y});
            }
            buf[r_in_blk][pad(8 * p + k)] = make_float2(c.re, c.im);
        }
    }
    __syncthreads();

    // ---- stage 1: n=64, s=8. p = lane>>3, q = lane&7. buf -> regs -> buf ----
    {
        const int p = lane >> 3, q = lane & 7;
        cplx a[8], b[8];
        #pragma unroll
        for (int r = 0; r < 8; r++) {
            float2 v = buf[r_in_blk][pad(q + 8 * p + 64 * r)];
            a[r] = {v.x, v.y};
        }
        __syncthreads();   // all reads done before in-place overwrite
        dft8(a, b);
        #pragma unroll
        for (int k = 0; k < 8; k++) {
            cplx c;
            if (k == 0) c = b[0];
            else {
                float2 t = tw[8 * p * k];      // exp(-2*pi*i*p*k/64)
                c = cmul(b[k], cplx{t.x, t.y});
            }
            buf[r_in_blk][pad(q + 64 * p + 8 * k)] = make_float2(c.re, c.im);
        }
    }
    __syncthreads();

    // ---- stage 2: n=8, s=64. twiddle==1. buf -> gmem ----
    {
        cplx a[8], b[8];
        #pragma unroll
        for (int r = 0; r < 8; r++) {
            float2 v = buf[r_in_blk][pad(lane + 64 * r)];
            a[r] = {v.x, v.y};
        }
        dft8(a, b);
        if (valid) {
            float2* o = out + row * NFFT;      // interleaved (re, im) = stack(..., -1)
            #pragma unroll
            for (int k = 0; k < 8; k++)
                __stcs(o + lane + 64 * k, make_float2(b[k].re, b[k].im));
        }
    }
}

extern "C" void kernel_launch(void* const* d_in, const int* in_sizes, int n_in,
                              void* d_out, int out_size) {
    const float* xre = (const float*)d_in[0];
    const float* xim = (const float*)d_in[1];
    const float* wre = (const float*)d_in[2];
    const float* wim = (const float*)d_in[3];
    (void)n_in; (void)out_size;

    int nrows = in_sizes[0] / NFFT;   // 8*16*256 = 32768
    int grid  = (nrows + ROWS_PER_BLK - 1) / ROWS_PER_BLK;
    range_fft512_kernel<<<grid, THREADS>>>(xre, xim, wre, wim, (float2*)d_out, nrows);
}